// round 3
// baseline (speedup 1.0000x reference)
#include <cuda_runtime.h>

#define D 2048
#define D4 (D / 4)
#define THREADS 512
#define NWARP (THREADS / 32)

__global__ __launch_bounds__(THREADS, 3) void fc_kernel(
    const float* __restrict__ feat, const float* __restrict__ pos,
    float* __restrict__ out)
{
    __shared__ float sred[9][NWARP];

    const int b = blockIdx.x;
    const int t = threadIdx.x;     // 0..511 == float4 index within a feature row
    const float4* __restrict__ feat4 = reinterpret_cast<const float4*>(feat);
    const float4* __restrict__ pos4  = reinterpret_cast<const float4*>(pos);
    float4* __restrict__ out4 = reinterpret_cast<float4*>(out);

    const long base = (long)b * 3 * D4;

    float4 f1 = feat4[base + 0 * D4 + t];
    float4 f2 = feat4[base + 1 * D4 + t];
    float4 f3 = feat4[base + 2 * D4 + t];
    const float4 p0 = __ldg(&pos4[0 * D4 + t]);
    const float4 p1 = __ldg(&pos4[1 * D4 + t]);
    const float4 p2 = __ldg(&pos4[2 * D4 + t]);
    f1.x += p0.x; f1.y += p0.y; f1.z += p0.z; f1.w += p0.w;
    f2.x += p1.x; f2.y += p1.y; f2.z += p1.z; f2.w += p1.w;
    f3.x += p2.x; f3.y += p2.y; f3.z += p2.z; f3.w += p2.w;

    // 9 reductions: |f1|^2 |f2|^2 |f3|^2  f1.f2 f1.f3 f2.f3  sum f1 f2 f3
    float acc[9];
#pragma unroll
    for (int k = 0; k < 9; k++) acc[k] = 0.0f;
    {
        const float ax[4] = {f1.x, f1.y, f1.z, f1.w};
        const float bx[4] = {f2.x, f2.y, f2.z, f2.w};
        const float cx[4] = {f3.x, f3.y, f3.z, f3.w};
#pragma unroll
        for (int k = 0; k < 4; k++) {
            const float fa = ax[k], fb = bx[k], fc = cx[k];
            acc[0] = fmaf(fa, fa, acc[0]);
            acc[1] = fmaf(fb, fb, acc[1]);
            acc[2] = fmaf(fc, fc, acc[2]);
            acc[3] = fmaf(fa, fb, acc[3]);
            acc[4] = fmaf(fa, fc, acc[4]);
            acc[5] = fmaf(fb, fc, acc[5]);
            acc[6] += fa;
            acc[7] += fb;
            acc[8] += fc;
        }
    }

    // warp butterfly reduce
#pragma unroll
    for (int k = 0; k < 9; k++) {
#pragma unroll
        for (int o = 16; o > 0; o >>= 1)
            acc[k] += __shfl_xor_sync(0xffffffffu, acc[k], o);
    }

    const int warp = t >> 5, lane = t & 31;
    if (lane == 0) {
#pragma unroll
        for (int k = 0; k < 9; k++) sred[k][warp] = acc[k];
    }
    __syncthreads();

    // Every thread redundantly finishes the reduction (broadcast LDS) and
    // computes the 6 coefficients — no serial thread-0 segment, no 2nd barrier.
    float S[9];
#pragma unroll
    for (int k = 0; k < 9; k++) {
        float s = sred[k][0];
#pragma unroll
        for (int w = 1; w < NWARP; w++) s += sred[k][w];
        S[k] = s;
    }
    const float d11 = S[0], d22 = S[1], d33 = S[2];
    const float d12 = S[3], d13 = S[4], d23 = S[5];
    const float s1 = S[6], s2 = S[7], s3 = S[8];

    const float e   = 1e-6f;
    const float De2 = (float)D * 1e-12f;
    // ||a-b+e||^2 = |a|^2+|b|^2-2ab + 2e(sa-sb) + D e^2
    const float q12 = d11 + d22 - 2.0f * d12 + De2;
    const float q13 = d11 + d33 - 2.0f * d13 + De2;
    const float q23 = d22 + d33 - 2.0f * d23 + De2;

    const float w12f = __fdividef(1.0f, 1.0f + sqrtf(fmaxf(q12 + 2.0f * e * (s1 - s2), 0.0f)));
    const float w12b = __fdividef(1.0f, 1.0f + sqrtf(fmaxf(q12 + 2.0f * e * (s2 - s1), 0.0f)));
    const float w13f = __fdividef(1.0f, 1.0f + sqrtf(fmaxf(q13 + 2.0f * e * (s1 - s3), 0.0f)));
    const float w13b = __fdividef(1.0f, 1.0f + sqrtf(fmaxf(q13 + 2.0f * e * (s3 - s1), 0.0f)));
    const float w23f = __fdividef(1.0f, 1.0f + sqrtf(fmaxf(q23 + 2.0f * e * (s2 - s3), 0.0f)));
    const float w23b = __fdividef(1.0f, 1.0f + sqrtf(fmaxf(q23 + 2.0f * e * (s3 - s2), 0.0f)));

    const float n1 = fmaxf(sqrtf(d11), 1e-8f);
    const float n2 = fmaxf(sqrtf(d22), 1e-8f);
    const float n3 = fmaxf(sqrtf(d33), 1e-8f);
    const float c12 = 0.5f + 0.5f * __fdividef(d12, n1 * n2);
    const float c13 = 0.5f + 0.5f * __fdividef(d13, n1 * n3);
    const float c23 = 0.5f + 0.5f * __fdividef(d23, n2 * n3);

    const float a12 = w12f + c12;  // o1 coeff on f2
    const float a13 = w13f + c13;  // o1 coeff on f3
    const float a21 = w12b + c12;  // o2 coeff on f1
    const float a23 = w23f + c23;  // o2 coeff on f3
    const float a31 = w13b + c13;  // o3 coeff on f1
    const float a32 = w23b + c23;  // o3 coeff on f2

    float4 o1, o2, o3;
    o1.x = fmaf(a12, f2.x, fmaf(a13, f3.x, f1.x));
    o1.y = fmaf(a12, f2.y, fmaf(a13, f3.y, f1.y));
    o1.z = fmaf(a12, f2.z, fmaf(a13, f3.z, f1.z));
    o1.w = fmaf(a12, f2.w, fmaf(a13, f3.w, f1.w));
    o2.x = fmaf(a21, f1.x, fmaf(a23, f3.x, f2.x));
    o2.y = fmaf(a21, f1.y, fmaf(a23, f3.y, f2.y));
    o2.z = fmaf(a21, f1.z, fmaf(a23, f3.z, f2.z));
    o2.w = fmaf(a21, f1.w, fmaf(a23, f3.w, f2.w));
    o3.x = fmaf(a31, f1.x, fmaf(a32, f2.x, f3.x));
    o3.y = fmaf(a31, f1.y, fmaf(a32, f2.y, f3.y));
    o3.z = fmaf(a31, f1.z, fmaf(a32, f2.z, f3.z));
    o3.w = fmaf(a31, f1.w, fmaf(a32, f2.w, f3.w));
    out4[base + 0 * D4 + t] = o1;
    out4[base + 1 * D4 + t] = o2;
    out4[base + 2 * D4 + t] = o3;
}

extern "C" void kernel_launch(void* const* d_in, const int* in_sizes, int n_in,
                              void* d_out, int out_size) {
    const float* feat = (const float*)d_in[0];
    const float* pos  = (const float*)d_in[1];
    float* out = (float*)d_out;
    const int B = in_sizes[0] / (3 * D);
    fc_kernel<<<B, THREADS>>>(feat, pos, out);
}

// round 4
// speedup vs baseline: 1.3065x; 1.3065x over previous
#include <cuda_runtime.h>

#define D 2048
#define D4 (D / 4)
#define THREADS 256
#define NWARP (THREADS / 32)
#define NV 2   // float4 chunks per thread per feature: 2048/4/256 = 2

__global__ __launch_bounds__(THREADS, 3) void fc_kernel(
    const float4* __restrict__ feat4, const float4* __restrict__ pos4,
    float4* __restrict__ out4, int B, int rows_per)
{
    __shared__ float4 spos[3 * D4];     // 24 KB, loaded once per CTA
    __shared__ float sred[9][NWARP];
    __shared__ float salpha[6];

    const int t = threadIdx.x;
    for (int i = t; i < 3 * D4; i += THREADS) spos[i] = pos4[i];

    int row = blockIdx.x * rows_per;
    const int row_end = min(row + rows_per, B);
    __syncthreads();
    if (row >= row_end) return;

    const int warp = t >> 5, lane = t & 31;

    // preload first row (f1|f2|f3, NV float4 each)
    float4 cur[6];
    {
        const long base = (long)row * (3 * D4);
#pragma unroll
        for (int q = 0; q < 3; q++)
#pragma unroll
            for (int v = 0; v < NV; v++)
                cur[q * NV + v] = __ldcs(&feat4[base + q * D4 + t + v * THREADS]);
    }

    while (true) {
        const int nrow = row + 1;
        const bool have_next = (nrow < row_end);

        // ---- prefetch next row while we reduce/store this one ----
        float4 nxt[6];
        if (have_next) {
            const long nbase = (long)nrow * (3 * D4);
#pragma unroll
            for (int q = 0; q < 3; q++)
#pragma unroll
                for (int v = 0; v < NV; v++)
                    nxt[q * NV + v] = __ldcs(&feat4[nbase + q * D4 + t + v * THREADS]);
        }

        // ---- add pos (smem) into cur ----
#pragma unroll
        for (int q = 0; q < 3; q++)
#pragma unroll
            for (int v = 0; v < NV; v++) {
                const float4 p = spos[q * D4 + t + v * THREADS];
                float4& f = cur[q * NV + v];
                f.x += p.x; f.y += p.y; f.z += p.z; f.w += p.w;
            }

        // ---- 9 reductions: |f1|^2 |f2|^2 |f3|^2 f1.f2 f1.f3 f2.f3 sum f1 f2 f3 ----
        float acc[9];
#pragma unroll
        for (int k = 0; k < 9; k++) acc[k] = 0.0f;
#pragma unroll
        for (int v = 0; v < NV; v++) {
            const float4 A = cur[0 * NV + v], Bq = cur[1 * NV + v], C = cur[2 * NV + v];
            const float ax[4] = {A.x, A.y, A.z, A.w};
            const float bx[4] = {Bq.x, Bq.y, Bq.z, Bq.w};
            const float cx[4] = {C.x, C.y, C.z, C.w};
#pragma unroll
            for (int k = 0; k < 4; k++) {
                const float fa = ax[k], fb = bx[k], fc = cx[k];
                acc[0] = fmaf(fa, fa, acc[0]);
                acc[1] = fmaf(fb, fb, acc[1]);
                acc[2] = fmaf(fc, fc, acc[2]);
                acc[3] = fmaf(fa, fb, acc[3]);
                acc[4] = fmaf(fa, fc, acc[4]);
                acc[5] = fmaf(fb, fc, acc[5]);
                acc[6] += fa;
                acc[7] += fb;
                acc[8] += fc;
            }
        }
#pragma unroll
        for (int k = 0; k < 9; k++) {
#pragma unroll
            for (int o = 16; o > 0; o >>= 1)
                acc[k] += __shfl_xor_sync(0xffffffffu, acc[k], o);
        }
        if (lane == 0) {
#pragma unroll
            for (int k = 0; k < 9; k++) sred[k][warp] = acc[k];
        }
        __syncthreads();

        // ---- thread-0 epilogue (fast-math: MUFU rsqrt only) ----
        if (t == 0) {
            float S[9];
#pragma unroll
            for (int k = 0; k < 9; k++) {
                float s = sred[k][0];
#pragma unroll
                for (int w = 1; w < NWARP; w++) s += sred[k][w];
                S[k] = s;
            }
            const float d11 = S[0], d22 = S[1], d33 = S[2];
            const float d12 = S[3], d13 = S[4], d23 = S[5];
            const float s1 = S[6], s2 = S[7], s3 = S[8];

            const float e   = 1e-6f;
            const float De2 = (float)D * 1e-12f;
            // ||a-b+e||^2 = |a|^2+|b|^2-2ab + 2e(sa-sb) + D e^2
            const float q12 = d11 + d22 - 2.0f * d12 + De2;
            const float q13 = d11 + d33 - 2.0f * d13 + De2;
            const float q23 = d22 + d33 - 2.0f * d23 + De2;

            const float t12f = fmaxf(q12 + 2.0f * e * (s1 - s2), 1e-30f);
            const float t12b = fmaxf(q12 + 2.0f * e * (s2 - s1), 1e-30f);
            const float t13f = fmaxf(q13 + 2.0f * e * (s1 - s3), 1e-30f);
            const float t13b = fmaxf(q13 + 2.0f * e * (s3 - s1), 1e-30f);
            const float t23f = fmaxf(q23 + 2.0f * e * (s2 - s3), 1e-30f);
            const float t23b = fmaxf(q23 + 2.0f * e * (s3 - s2), 1e-30f);

            // sqrt(x) = x * rsqrt(x); 1/(1+s) via fast divide
            const float w12f = __fdividef(1.0f, 1.0f + t12f * rsqrtf(t12f));
            const float w12b = __fdividef(1.0f, 1.0f + t12b * rsqrtf(t12b));
            const float w13f = __fdividef(1.0f, 1.0f + t13f * rsqrtf(t13f));
            const float w13b = __fdividef(1.0f, 1.0f + t13b * rsqrtf(t13b));
            const float w23f = __fdividef(1.0f, 1.0f + t23f * rsqrtf(t23f));
            const float w23b = __fdividef(1.0f, 1.0f + t23b * rsqrtf(t23b));

            // cos terms: 0.5 + 0.5*dij*rsqrt(dii*djj) (norms >> EPS_CS for this data)
            const float c12 = 0.5f + 0.5f * d12 * rsqrtf(fmaxf(d11 * d22, 1e-30f));
            const float c13 = 0.5f + 0.5f * d13 * rsqrtf(fmaxf(d11 * d33, 1e-30f));
            const float c23 = 0.5f + 0.5f * d23 * rsqrtf(fmaxf(d22 * d33, 1e-30f));

            salpha[0] = w12f + c12;  // o1 coeff on f2
            salpha[1] = w13f + c13;  // o1 coeff on f3
            salpha[2] = w12b + c12;  // o2 coeff on f1
            salpha[3] = w23f + c23;  // o2 coeff on f3
            salpha[4] = w13b + c13;  // o3 coeff on f1
            salpha[5] = w23b + c23;  // o3 coeff on f2
        }
        __syncthreads();

        const float a12 = salpha[0], a13 = salpha[1];
        const float a21 = salpha[2], a23 = salpha[3];
        const float a31 = salpha[4], a32 = salpha[5];

        // ---- store outputs ----
        const long base = (long)row * (3 * D4);
#pragma unroll
        for (int v = 0; v < NV; v++) {
            const int i = t + v * THREADS;
            const float4 f1 = cur[0 * NV + v], f2 = cur[1 * NV + v], f3 = cur[2 * NV + v];
            float4 o1, o2, o3;
            o1.x = fmaf(a12, f2.x, fmaf(a13, f3.x, f1.x));
            o1.y = fmaf(a12, f2.y, fmaf(a13, f3.y, f1.y));
            o1.z = fmaf(a12, f2.z, fmaf(a13, f3.z, f1.z));
            o1.w = fmaf(a12, f2.w, fmaf(a13, f3.w, f1.w));
            o2.x = fmaf(a21, f1.x, fmaf(a23, f3.x, f2.x));
            o2.y = fmaf(a21, f1.y, fmaf(a23, f3.y, f2.y));
            o2.z = fmaf(a21, f1.z, fmaf(a23, f3.z, f2.z));
            o2.w = fmaf(a21, f1.w, fmaf(a23, f3.w, f2.w));
            o3.x = fmaf(a31, f1.x, fmaf(a32, f2.x, f3.x));
            o3.y = fmaf(a31, f1.y, fmaf(a32, f2.y, f3.y));
            o3.z = fmaf(a31, f1.z, fmaf(a32, f2.z, f3.z));
            o3.w = fmaf(a31, f1.w, fmaf(a32, f2.w, f3.w));
            __stcs(&out4[base + 0 * D4 + i], o1);
            __stcs(&out4[base + 1 * D4 + i], o2);
            __stcs(&out4[base + 2 * D4 + i], o3);
        }

        if (!have_next) break;
#pragma unroll
        for (int k = 0; k < 6; k++) cur[k] = nxt[k];
        row = nrow;
    }
}

extern "C" void kernel_launch(void* const* d_in, const int* in_sizes, int n_in,
                              void* d_out, int out_size) {
    const float* feat = (const float*)d_in[0];
    const float* pos  = (const float*)d_in[1];
    float* out = (float*)d_out;
    const int B = in_sizes[0] / (3 * D);

    int sm_count = 148;
    cudaDeviceGetAttribute(&sm_count, cudaDevAttrMultiProcessorCount, 0);

    int grid = sm_count * 3;          // exactly resident (launch_bounds occ=3)
    if (grid > B) grid = B;
    const int rows_per = (B + grid - 1) / grid;

    fc_kernel<<<grid, THREADS>>>(
        reinterpret_cast<const float4*>(feat),
        reinterpret_cast<const float4*>(pos),
        reinterpret_cast<float4*>(out), B, rows_per);
}